// round 1
// baseline (speedup 1.0000x reference)
#include <cuda_runtime.h>

// GLoss: g_loss + p_loss + g_d_loss, fused single pass.
//
// d  = output - target (full res)       -> gradient-of-d squared + d^2
// dd = maxpool2(output) - maxpool2(target) -> gradient-of-dd squared
//
// Tile: 32x32 full-res pixels per block, halo of 2 (36x36 smem), which also
// provides the half-res tile (16x16) with halo 1 (18x18 dd values).

#define TILE 32
#define SW 36          // TILE + 2*2 halo
#define IMG 1024
#define HIMG 512
#define NIMG 8

__device__ double g_accum[3];   // [grad_full, pixel, grad_half] raw sums

__global__ void gloss_zero() {
    if (threadIdx.x < 3) g_accum[threadIdx.x] = 0.0;
}

__global__ __launch_bounds__(1024, 1) void gloss_main(
    const float* __restrict__ img_o,
    const float* __restrict__ img_t)
{
    __shared__ float so[SW][SW + 1];
    __shared__ float st[SW][SW + 1];
    __shared__ float sd[SW][SW + 1];
    __shared__ float sdd[18][19];
    __shared__ float red[32][3];

    const int b   = blockIdx.z;
    const int ty0 = blockIdx.y * TILE;
    const int tx0 = blockIdx.x * TILE;
    const int tid = threadIdx.y * 32 + threadIdx.x;
    const size_t base = (size_t)b * IMG * IMG;

    // ---- load 36x36 halo tile of both images; 0 outside image ----
    #pragma unroll
    for (int idx = tid; idx < SW * SW; idx += 1024) {
        int ly = idx / SW, lx = idx - ly * SW;
        int gy = ty0 - 2 + ly, gx = tx0 - 2 + lx;
        float o = 0.f, t = 0.f;
        if (gy >= 0 && gy < IMG && gx >= 0 && gx < IMG) {
            size_t p = base + (size_t)gy * IMG + gx;
            o = img_o[p];
            t = img_t[p];
        }
        so[ly][lx] = o;
        st[ly][lx] = t;
        sd[ly][lx] = o - t;
    }
    __syncthreads();

    // ---- full-res: pixel loss + 8-direction gradient loss on d ----
    const int iy = threadIdx.y + 2;
    const int ix = threadIdx.x + 2;
    float dc = sd[iy][ix];
    float psum = dc * dc;
    float gsum = 0.f;
    {
        float e;
        e = dc - sd[iy - 1][ix - 1]; gsum += e * e;
        e = dc - sd[iy - 1][ix    ]; gsum += e * e;
        e = dc - sd[iy - 1][ix + 1]; gsum += e * e;
        e = dc - sd[iy    ][ix - 1]; gsum += e * e;
        e = dc - sd[iy    ][ix + 1]; gsum += e * e;
        e = dc - sd[iy + 1][ix - 1]; gsum += e * e;
        e = dc - sd[iy + 1][ix    ]; gsum += e * e;
        e = dc - sd[iy + 1][ix + 1]; gsum += e * e;
    }

    // ---- half-res dd = maxpool2(o) - maxpool2(t), 18x18 with halo 1 ----
    if (tid < 18 * 18) {
        int hly = tid / 18, hlx = tid - hly * 18;
        int hgy = (ty0 >> 1) - 1 + hly;
        int hgx = (tx0 >> 1) - 1 + hlx;
        float v = 0.f;
        if (hgy >= 0 && hgy < HIMG && hgx >= 0 && hgx < HIMG) {
            int fy = 2 * hly, fx = 2 * hlx;  // local full-res coords
            float mo = fmaxf(fmaxf(so[fy][fx], so[fy][fx + 1]),
                             fmaxf(so[fy + 1][fx], so[fy + 1][fx + 1]));
            float mt = fmaxf(fmaxf(st[fy][fx], st[fy][fx + 1]),
                             fmaxf(st[fy + 1][fx], st[fy + 1][fx + 1]));
            v = mo - mt;
        }
        sdd[hly][hlx] = v;
    }
    __syncthreads();

    // ---- half-res 8-direction gradient loss on dd (16x16 interior) ----
    float gdsum = 0.f;
    if (tid < 256) {
        int hy = (tid >> 4) + 1, hx = (tid & 15) + 1;
        float c = sdd[hy][hx];
        float e;
        e = c - sdd[hy - 1][hx - 1]; gdsum += e * e;
        e = c - sdd[hy - 1][hx    ]; gdsum += e * e;
        e = c - sdd[hy - 1][hx + 1]; gdsum += e * e;
        e = c - sdd[hy    ][hx - 1]; gdsum += e * e;
        e = c - sdd[hy    ][hx + 1]; gdsum += e * e;
        e = c - sdd[hy + 1][hx - 1]; gdsum += e * e;
        e = c - sdd[hy + 1][hx    ]; gdsum += e * e;
        e = c - sdd[hy + 1][hx + 1]; gdsum += e * e;
    }

    // ---- block reduction of (gsum, psum, gdsum) ----
    #pragma unroll
    for (int off = 16; off; off >>= 1) {
        gsum  += __shfl_down_sync(0xFFFFFFFFu, gsum,  off);
        psum  += __shfl_down_sync(0xFFFFFFFFu, psum,  off);
        gdsum += __shfl_down_sync(0xFFFFFFFFu, gdsum, off);
    }
    if ((tid & 31) == 0) {
        red[tid >> 5][0] = gsum;
        red[tid >> 5][1] = psum;
        red[tid >> 5][2] = gdsum;
    }
    __syncthreads();
    if (tid < 32) {
        gsum  = red[tid][0];
        psum  = red[tid][1];
        gdsum = red[tid][2];
        #pragma unroll
        for (int off = 16; off; off >>= 1) {
            gsum  += __shfl_down_sync(0xFFFFFFFFu, gsum,  off);
            psum  += __shfl_down_sync(0xFFFFFFFFu, psum,  off);
            gdsum += __shfl_down_sync(0xFFFFFFFFu, gdsum, off);
        }
        if (tid == 0) {
            atomicAdd(&g_accum[0], (double)gsum);
            atomicAdd(&g_accum[1], (double)psum);
            atomicAdd(&g_accum[2], (double)gdsum);
        }
    }
}

__global__ void gloss_finalize(float* out) {
    double g  = g_accum[0] / (8.0 * (double)NIMG * IMG * IMG);
    double p  = g_accum[1] / ((double)NIMG * IMG * IMG);
    double gd = g_accum[2] / (8.0 * (double)NIMG * HIMG * HIMG);
    out[0] = (float)(g + p + gd);
}

extern "C" void kernel_launch(void* const* d_in, const int* in_sizes, int n_in,
                              void* d_out, int out_size) {
    const float* img_o = (const float*)d_in[0];
    const float* img_t = (const float*)d_in[1];
    float* out = (float*)d_out;

    gloss_zero<<<1, 32>>>();
    dim3 grid(IMG / TILE, IMG / TILE, NIMG);
    dim3 block(32, 32);
    gloss_main<<<grid, block>>>(img_o, img_t);
    gloss_finalize<<<1, 1>>>(out);
}

// round 2
// speedup vs baseline: 3.0453x; 3.0453x over previous
#include <cuda_runtime.h>

// GLoss fused: g_loss + p_loss + g_d_loss.
//   d  = output - target            -> mean over 8 dirs of grad(d)^2, + mean d^2
//   dd = maxpool2(o) - maxpool2(t)  -> mean over 8 dirs of grad(dd)^2
//
// 64x64 full-res tile per 256-thread block. Load region: rows [ty0-2, ty0+66),
// cols [tx0-4, tx0+68) (x-halo widened to 4 for float4 alignment). During the
// load phase each "unit" (2 rows x 4 cols) computes d into smem and the two
// pooled dd values into smem. No so/st smem needed.

#define IMG   1024
#define HIMG  512
#define NIMG  8
#define TILE  64
#define GRIDX (IMG / TILE)          // 16
#define NBLK  (GRIDX * GRIDX * NIMG) // 2048

#define LH    68      // loaded rows  (halo 2 top/bottom)
#define QX    18      // float4 units per row (72 cols)
#define SDP   76      // sd row stride (mult of 4 -> float4-aligned every row)
#define DDP   38      // sdd row stride (even -> float2-aligned)

__device__ float g_part[3 * NBLK];

__global__ __launch_bounds__(256) void gloss_main(
    const float* __restrict__ img_o,
    const float* __restrict__ img_t)
{
    __shared__ float sd[LH * SDP];        // d with halo: 68 x 72 used
    __shared__ float sdd[34 * DDP];       // dd with halo: 34 x 36 used
    __shared__ float red[8][3];

    const int tid = threadIdx.x;
    const int ty0 = blockIdx.y * TILE;
    const int tx0 = blockIdx.x * TILE;
    const size_t base = (size_t)blockIdx.z * IMG * IMG;

    // ---------- load phase: 34 quad-rows x 18 float4 units ----------
    #pragma unroll 1
    for (int u = tid; u < 34 * QX; u += 256) {
        int qy = u / QX;
        int ux = u - qy * QX;
        int gy = ty0 - 2 + 2 * qy;        // even
        int gx = tx0 - 4 + 4 * ux;        // mult of 4
        float4 o0, o1, t0, t1;
        bool in = (gy >= 0) & (gy < IMG) & (gx >= 0) & (gx < IMG);
        if (in) {
            size_t p0 = base + (size_t)gy * IMG + gx;
            o0 = *(const float4*)(img_o + p0);
            o1 = *(const float4*)(img_o + p0 + IMG);
            t0 = *(const float4*)(img_t + p0);
            t1 = *(const float4*)(img_t + p0 + IMG);
        } else {
            o0 = o1 = t0 = t1 = make_float4(0.f, 0.f, 0.f, 0.f);
        }
        // d values (2 rows x 4 cols)
        float4 d0 = make_float4(o0.x - t0.x, o0.y - t0.y, o0.z - t0.z, o0.w - t0.w);
        float4 d1 = make_float4(o1.x - t1.x, o1.y - t1.y, o1.z - t1.z, o1.w - t1.w);
        int sy = 2 * qy, sx = 4 * ux;
        *(float4*)(sd + sy * SDP + sx)       = d0;
        *(float4*)(sd + (sy + 1) * SDP + sx) = d1;
        // pooled dd (2 half-res values)
        float mo0 = fmaxf(fmaxf(o0.x, o0.y), fmaxf(o1.x, o1.y));
        float mt0 = fmaxf(fmaxf(t0.x, t0.y), fmaxf(t1.x, t1.y));
        float mo1 = fmaxf(fmaxf(o0.z, o0.w), fmaxf(o1.z, o1.w));
        float mt1 = fmaxf(fmaxf(t0.z, t0.w), fmaxf(t1.z, t1.w));
        *(float2*)(sdd + qy * DDP + 2 * ux) = make_float2(mo0 - mt0, mo1 - mt1);
    }
    __syncthreads();

    // ---------- full-res: pixel loss + 8-dir gradient on d ----------
    // interior pixel (y,x) in 0..63 -> sd[(y+2)*SDP + x+4]
    float gsum = 0.f, psum = 0.f, gdsum = 0.f;
    {
        int y  = tid >> 2;
        int x0 = (tid & 3) << 4;
        const float* r0 = sd + (y + 1) * SDP + x0 + 3;  // row above, col x-1
        const float* r1 = sd + (y + 2) * SDP + x0 + 3;
        const float* r2 = sd + (y + 3) * SDP + x0 + 3;
        #pragma unroll
        for (int x = 0; x < 16; x++) {
            float c = r1[x + 1];
            psum = fmaf(c, c, psum);
            float e;
            e = c - r0[x];     gsum = fmaf(e, e, gsum);
            e = c - r0[x + 1]; gsum = fmaf(e, e, gsum);
            e = c - r0[x + 2]; gsum = fmaf(e, e, gsum);
            e = c - r1[x];     gsum = fmaf(e, e, gsum);
            e = c - r1[x + 2]; gsum = fmaf(e, e, gsum);
            e = c - r2[x];     gsum = fmaf(e, e, gsum);
            e = c - r2[x + 1]; gsum = fmaf(e, e, gsum);
            e = c - r2[x + 2]; gsum = fmaf(e, e, gsum);
        }
    }

    // ---------- half-res: 8-dir gradient on dd ----------
    // interior (hy,hx) in 0..31 -> sdd[(hy+1)*DDP + hx+2]
    {
        int hy  = tid >> 3;
        int hx0 = (tid & 7) << 2;
        const float* r0 = sdd + hy * DDP + hx0 + 1;        // row above, col hx-1
        const float* r1 = sdd + (hy + 1) * DDP + hx0 + 1;
        const float* r2 = sdd + (hy + 2) * DDP + hx0 + 1;
        #pragma unroll
        for (int x = 0; x < 4; x++) {
            float c = r1[x + 1];
            float e;
            e = c - r0[x];     gdsum = fmaf(e, e, gdsum);
            e = c - r0[x + 1]; gdsum = fmaf(e, e, gdsum);
            e = c - r0[x + 2]; gdsum = fmaf(e, e, gdsum);
            e = c - r1[x];     gdsum = fmaf(e, e, gdsum);
            e = c - r1[x + 2]; gdsum = fmaf(e, e, gdsum);
            e = c - r2[x];     gdsum = fmaf(e, e, gdsum);
            e = c - r2[x + 1]; gdsum = fmaf(e, e, gdsum);
            e = c - r2[x + 2]; gdsum = fmaf(e, e, gdsum);
        }
    }

    // ---------- block reduction ----------
    #pragma unroll
    for (int off = 16; off; off >>= 1) {
        gsum  += __shfl_down_sync(0xFFFFFFFFu, gsum,  off);
        psum  += __shfl_down_sync(0xFFFFFFFFu, psum,  off);
        gdsum += __shfl_down_sync(0xFFFFFFFFu, gdsum, off);
    }
    int lane = tid & 31, warp = tid >> 5;
    if (lane == 0) {
        red[warp][0] = gsum;
        red[warp][1] = psum;
        red[warp][2] = gdsum;
    }
    __syncthreads();
    if (tid < 32) {
        gsum  = (tid < 8) ? red[tid][0] : 0.f;
        psum  = (tid < 8) ? red[tid][1] : 0.f;
        gdsum = (tid < 8) ? red[tid][2] : 0.f;
        #pragma unroll
        for (int off = 4; off; off >>= 1) {
            gsum  += __shfl_down_sync(0xFFFFFFFFu, gsum,  off);
            psum  += __shfl_down_sync(0xFFFFFFFFu, psum,  off);
            gdsum += __shfl_down_sync(0xFFFFFFFFu, gdsum, off);
        }
        if (tid == 0) {
            int bid = (blockIdx.z * GRIDX + blockIdx.y) * GRIDX + blockIdx.x;
            g_part[bid]            = gsum;
            g_part[NBLK + bid]     = psum;
            g_part[2 * NBLK + bid] = gdsum;
        }
    }
}

__global__ __launch_bounds__(256) void gloss_finalize(float* __restrict__ out) {
    __shared__ float red[8][3];
    int tid = threadIdx.x;
    float s0 = 0.f, s1 = 0.f, s2 = 0.f;
    #pragma unroll
    for (int i = tid; i < NBLK; i += 256) {
        s0 += g_part[i];
        s1 += g_part[NBLK + i];
        s2 += g_part[2 * NBLK + i];
    }
    #pragma unroll
    for (int off = 16; off; off >>= 1) {
        s0 += __shfl_down_sync(0xFFFFFFFFu, s0, off);
        s1 += __shfl_down_sync(0xFFFFFFFFu, s1, off);
        s2 += __shfl_down_sync(0xFFFFFFFFu, s2, off);
    }
    int lane = tid & 31, warp = tid >> 5;
    if (lane == 0) { red[warp][0] = s0; red[warp][1] = s1; red[warp][2] = s2; }
    __syncthreads();
    if (tid < 32) {
        s0 = (tid < 8) ? red[tid][0] : 0.f;
        s1 = (tid < 8) ? red[tid][1] : 0.f;
        s2 = (tid < 8) ? red[tid][2] : 0.f;
        #pragma unroll
        for (int off = 4; off; off >>= 1) {
            s0 += __shfl_down_sync(0xFFFFFFFFu, s0, off);
            s1 += __shfl_down_sync(0xFFFFFFFFu, s1, off);
            s2 += __shfl_down_sync(0xFFFFFFFFu, s2, off);
        }
        if (tid == 0) {
            double g  = (double)s0 / (8.0 * (double)NIMG * IMG * IMG);
            double p  = (double)s1 / ((double)NIMG * IMG * IMG);
            double gd = (double)s2 / (8.0 * (double)NIMG * HIMG * HIMG);
            out[0] = (float)(g + p + gd);
        }
    }
}

extern "C" void kernel_launch(void* const* d_in, const int* in_sizes, int n_in,
                              void* d_out, int out_size) {
    const float* img_o = (const float*)d_in[0];
    const float* img_t = (const float*)d_in[1];
    dim3 grid(GRIDX, GRIDX, NIMG);
    gloss_main<<<grid, 256>>>(img_o, img_t);
    gloss_finalize<<<1, 256>>>((float*)d_out);
}